// round 11
// baseline (speedup 1.0000x reference)
#include <cuda_runtime.h>
#include <cstdint>
#include <cfloat>

#define N_NODES_MAX 100000
#define N_EDGES_MAX 1600000
#define FULL 0xFFFFFFFFu

typedef unsigned long long ull;

// ---------------- scratch (static device globals) ---------------------------
__device__ float4  g_h[N_NODES_MAX * 16];     // [N,64] projected features
__device__ float4  g_el[N_NODES_MAX];         // [N,4]
__device__ float4  g_er[N_NODES_MAX];         // [N,4]
__device__ int     g_cnt[N_NODES_MAX];        // in-degree
__device__ int     g_fill[N_NODES_MAX];       // scatter cursors
__device__ int     g_rowptr[N_NODES_MAX];     // exclusive prefix of cnt
__device__ int     g_blksum[128];
__device__ int     g_esrc[N_EDGES_MAX];       // CSR: src node per slot

__device__ __forceinline__ float leaky(float x) { return x > 0.f ? x : 0.2f * x; }

__device__ __forceinline__ ull pack2(float f) {
    ull r;
    asm("mov.b64 %0, {%1, %1};" : "=l"(r) : "f"(f));
    return r;
}
__device__ __forceinline__ void fma2(ull& acc, ull a, ull b) {
    asm("fma.rn.f32x2 %0, %1, %2, %0;" : "+l"(acc) : "l"(a), "l"(b));
}
__device__ __forceinline__ void unpack2(ull v, float& lo, float& hi) {
    asm("mov.b64 {%0, %1}, %2;" : "=f"(lo), "=f"(hi) : "l"(v));
}

// ---------------- kernel: zero counters -------------------------------------
__global__ void zero_kernel(int n_nodes) {
    int i = blockIdx.x * blockDim.x + threadIdx.x;
    if (i < n_nodes) { g_cnt[i] = 0; g_fill[i] = 0; }
}

// ---------------- kernel: in-degree histogram -------------------------------
__global__ void hist_kernel(const int* __restrict__ dst, int n_edges) {
    int e = blockIdx.x * blockDim.x + threadIdx.x;
    if (e < n_edges) atomicAdd(&g_cnt[dst[e]], 1);
}

// ---------------- scan: rowptr = exclusive_scan(cnt) ------------------------
__global__ __launch_bounds__(1024) void scan1_kernel(int n) {
    __shared__ int sh[1024];
    int i = blockIdx.x * 1024 + threadIdx.x;
    int v = (i < n) ? g_cnt[i] : 0;
    sh[threadIdx.x] = v;
    __syncthreads();
    for (int off = 1; off < 1024; off <<= 1) {
        int t = (threadIdx.x >= off) ? sh[threadIdx.x - off] : 0;
        __syncthreads();
        sh[threadIdx.x] += t;
        __syncthreads();
    }
    if (i < n) g_rowptr[i] = sh[threadIdx.x] - v;
    if (threadIdx.x == 1023) g_blksum[blockIdx.x] = sh[1023];
}
// merged scan2+scan3: each block computes prefix of blksum below it, adds.
__global__ __launch_bounds__(1024) void scan23_kernel(int n, int nb) {
    __shared__ int sh[128];
    const int t = threadIdx.x;
    if (t < 128) sh[t] = (t < nb && t < (int)blockIdx.x) ? g_blksum[t] : 0;
    __syncthreads();
    if (t < 64)  sh[t] += sh[t + 64];
    __syncthreads();
    if (t < 32) {
        int v = sh[t] + sh[t + 32];
#pragma unroll
        for (int o = 16; o; o >>= 1) v += __shfl_xor_sync(FULL, v, o);
        if (t == 0) sh[0] = v;
    }
    __syncthreads();
    const int off = sh[0];
    int i = blockIdx.x * 1024 + t;
    if (i < n) g_rowptr[i] += off;
}

// ---------------- kernel: CSR scatter ----------------------------------------
__global__ void scatter_kernel(const int* __restrict__ src,
                               const int* __restrict__ dst, int n_edges) {
    int e = blockIdx.x * blockDim.x + threadIdx.x;
    if (e >= n_edges) return;
    int d = dst[e];
    int r = atomicAdd(&g_fill[d], 1);
    g_esrc[g_rowptr[d] + r] = src[e];
}

// ---------------- kernel: h = feat @ W, el/er (double-buffered, f32x2) -------
// 256 threads, tile = 128 nodes x 64 cols. Thread (tx,ty) owns nodes tx*4..+3,
// cols ty*8..+7. featT staged in 32-k chunks; next chunk prefetched into
// registers while current chunk computes (hides DRAM latency).
#define FEATT_F   (32 * 128)
#define GEMM_SMEM_FLOATS (FEATT_F + 128 * 64 + 64 + 64 + 512 + 512)
__global__ __launch_bounds__(256, 3)
void gemm_kernel(const float* __restrict__ feat, const float* __restrict__ W,
                 const float* __restrict__ attn_l, const float* __restrict__ attn_r,
                 int n_nodes) {
    extern __shared__ float smem[];
    float* featT = smem;                       // [k%32][node] 32x128
    float* Wsh   = smem + FEATT_F;             // [k][col]  128x64
    float* alS   = Wsh + 8192;                 // 64
    float* arS   = alS + 64;                   // 64
    float* elS   = arS + 64;                   // [node][head] 128x4
    float* erS   = elS + 512;                  // 128x4

    const int tid  = threadIdx.x;
    const int tx   = tid & 31;
    const int ty   = tid >> 5;
    const int base = blockIdx.x * 128;

    for (int i = tid; i < 128 * 64; i += 256) Wsh[i] = W[i];
    if (tid < 64) { alS[tid] = attn_l[tid]; arS[tid] = attn_r[tid]; }
    if (tid < 128) {
        float4 z = make_float4(0.f, 0.f, 0.f, 0.f);
        ((float4*)elS)[tid] = z;
        ((float4*)erS)[tid] = z;
    }

    ull acc2[16];
#pragma unroll
    for (int j = 0; j < 16; j++) acc2[j] = 0ull;

    const float4* feat4 = (const float4*)feat;
    const int row  = tid & 127;          // staging row (node within tile)
    const int c4b  = tid >> 7;           // staging k4 base (0..1)
    const int node_s = base + row;
    const bool valid_s = (node_s < n_nodes);

    float4 pf[4];
    // prefetch chunk 0
#pragma unroll
    for (int j = 0; j < 4; j++) {
        int c4 = c4b + j * 2;
        pf[j] = valid_s ? feat4[node_s * 32 + 0 * 8 + c4]
                        : make_float4(0.f, 0.f, 0.f, 0.f);
    }

    for (int c = 0; c < 4; c++) {
        if (c) __syncthreads();          // previous chunk fully consumed
        // store staged registers -> featT (transposed)
#pragma unroll
        for (int j = 0; j < 4; j++) {
            int c4 = c4b + j * 2;
            featT[(c4 * 4 + 0) * 128 + row] = pf[j].x;
            featT[(c4 * 4 + 1) * 128 + row] = pf[j].y;
            featT[(c4 * 4 + 2) * 128 + row] = pf[j].z;
            featT[(c4 * 4 + 3) * 128 + row] = pf[j].w;
        }
        __syncthreads();
        // prefetch next chunk: DRAM latency overlaps with compute below
        if (c < 3) {
#pragma unroll
            for (int j = 0; j < 4; j++) {
                int c4 = c4b + j * 2;
                pf[j] = valid_s ? feat4[node_s * 32 + (c + 1) * 8 + c4]
                                : make_float4(0.f, 0.f, 0.f, 0.f);
            }
        }

#pragma unroll 8
        for (int k = 0; k < 32; k++) {
            float4 f = *(const float4*)&featT[k * 128 + tx * 4];
            ull fd0 = pack2(f.x), fd1 = pack2(f.y);
            ull fd2 = pack2(f.z), fd3 = pack2(f.w);
            const ulonglong2* Wv =
                (const ulonglong2*)&Wsh[(c * 32 + k) * 64 + ty * 8];
            ulonglong2 wa = Wv[0];
            ulonglong2 wb = Wv[1];
            fma2(acc2[0],  fd0, wa.x); fma2(acc2[1],  fd0, wa.y);
            fma2(acc2[2],  fd0, wb.x); fma2(acc2[3],  fd0, wb.y);
            fma2(acc2[4],  fd1, wa.x); fma2(acc2[5],  fd1, wa.y);
            fma2(acc2[6],  fd1, wb.x); fma2(acc2[7],  fd1, wb.y);
            fma2(acc2[8],  fd2, wa.x); fma2(acc2[9],  fd2, wa.y);
            fma2(acc2[10], fd2, wb.x); fma2(acc2[11], fd2, wb.y);
            fma2(acc2[12], fd3, wa.x); fma2(acc2[13], fd3, wa.y);
            fma2(acc2[14], fd3, wb.x); fma2(acc2[15], fd3, wb.y);
        }
    }

    float o[4][8];
#pragma unroll
    for (int n = 0; n < 4; n++)
#pragma unroll
        for (int cp = 0; cp < 4; cp++)
            unpack2(acc2[n * 4 + cp], o[n][2 * cp], o[n][2 * cp + 1]);

    // partial el/er: this thread's 8 cols lie entirely in head ty>>1
    const int head = ty >> 1;
#pragma unroll
    for (int n = 0; n < 4; n++) {
        float sl = 0.f, sr = 0.f;
#pragma unroll
        for (int cc = 0; cc < 8; cc++) {
            int col = ty * 8 + cc;
            sl += o[n][cc] * alS[col];
            sr += o[n][cc] * arS[col];
        }
        int node_l = tx * 4 + n;
        atomicAdd(&elS[node_l * 4 + head], sl);
        atomicAdd(&erS[node_l * 4 + head], sr);
    }

    // store h (two STG.128 per node)
    float* g_h_f = (float*)g_h;
#pragma unroll
    for (int n = 0; n < 4; n++) {
        int node = base + tx * 4 + n;
        if (node < n_nodes) {
            float* p = g_h_f + node * 64 + ty * 8;
            *(float4*)p       = make_float4(o[n][0], o[n][1], o[n][2], o[n][3]);
            *(float4*)(p + 4) = make_float4(o[n][4], o[n][5], o[n][6], o[n][7]);
        }
    }

    __syncthreads();
    if (tid < 128) {
        int node = base + tid;
        if (node < n_nodes) {
            g_el[node] = ((const float4*)elS)[tid];
            g_er[node] = ((const float4*)erS)[tid];
        }
    }
}

// ---------------- kernel: fused softmax + aggregation ------------------------
// one warp per node. ex computed lane-parallel (1 edge per lane), staged in
// smem; serial agg loop = shfl(s) + LDS(ex) + LDG(h) + 2 FFMA per edge.
__global__ __launch_bounds__(256)
void node_kernel(const float* __restrict__ bias, float* __restrict__ out,
                 int n_nodes) {
    __shared__ float sm_ex[8][128];   // [warp][edge*4 + head]
    const int gwarp = (blockIdx.x * blockDim.x + threadIdx.x) >> 5;
    const int w     = (threadIdx.x >> 5);
    const int lane  = threadIdx.x & 31;
    if (gwarp >= n_nodes) return;

    const int base = g_rowptr[gwarp];
    const int deg  = g_cnt[gwarp];
    const int hd   = lane >> 3;

    const float2 b2 = ((const float2*)bias)[lane];
    float2* outp = (float2*)out + (gwarp * 32 + lane);
    if (deg == 0) { *outp = b2; return; }

    const float4 er4 = g_er[gwarp];
    const float2* h2 = (const float2*)g_h;

    float2 acc  = make_float2(0.f, 0.f);
    float4 den4 = make_float4(0.f, 0.f, 0.f, 0.f);

    const int nb = (deg + 31) >> 5;
    int s_reg = (lane < deg) ? g_esrc[base + lane] : 0;
    for (int b = 0; b < nb; b++) {
        const int cur = s_reg;
        const int cnt = min(32, deg - b * 32);
        const int noff = (b + 1) * 32;
        if (b + 1 < nb)
            s_reg = (noff + lane < deg) ? g_esrc[base + noff + lane] : 0;

        float4 ex = make_float4(0.f, 0.f, 0.f, 0.f);
        if (lane < cnt) {
            float4 a = g_el[cur];
            ex.x = __expf(leaky(a.x + er4.x));
            ex.y = __expf(leaky(a.y + er4.y));
            ex.z = __expf(leaky(a.z + er4.z));
            ex.w = __expf(leaky(a.w + er4.w));
        }
        den4.x += ex.x; den4.y += ex.y; den4.z += ex.z; den4.w += ex.w;
        __syncwarp();
        ((float4*)sm_ex[w])[lane] = ex;
        __syncwarp();

#pragma unroll 8
        for (int i = 0; i < cnt; i++) {
            int s = __shfl_sync(FULL, cur, i);
            float a = sm_ex[w][i * 4 + hd];
            float2 v = h2[s * 32 + lane];
            acc.x += a * v.x;
            acc.y += a * v.y;
        }
    }

#pragma unroll
    for (int o = 16; o; o >>= 1) {
        den4.x += __shfl_xor_sync(FULL, den4.x, o);
        den4.y += __shfl_xor_sync(FULL, den4.y, o);
        den4.z += __shfl_xor_sync(FULL, den4.z, o);
        den4.w += __shfl_xor_sync(FULL, den4.w, o);
    }
    const float den = hd == 0 ? den4.x : hd == 1 ? den4.y : hd == 2 ? den4.z : den4.w;
    const float rd = 1.f / den;
    *outp = make_float2(acc.x * rd + b2.x, acc.y * rd + b2.y);
}

// ---------------- launcher --------------------------------------------------
extern "C" void kernel_launch(void* const* d_in, const int* in_sizes, int n_in,
                              void* d_out, int out_size) {
    const float* feat   = (const float*)d_in[0];
    const float* W      = (const float*)d_in[1];
    const float* attn_l = (const float*)d_in[2];
    const float* attn_r = (const float*)d_in[3];
    const float* bias   = (const float*)d_in[4];
    const int*   src    = (const int*)d_in[5];
    const int*   dst    = (const int*)d_in[6];
    float*       out    = (float*)d_out;

    const int n_nodes = in_sizes[0] / 128;
    const int n_edges = in_sizes[5];
    const int nb      = (n_nodes + 1023) / 1024;

    cudaFuncSetAttribute(gemm_kernel, cudaFuncAttributeMaxDynamicSharedMemorySize,
                         GEMM_SMEM_FLOATS * (int)sizeof(float));

    // gemm placed 4th: ncu captures launch #4
    zero_kernel<<<(n_nodes + 255) / 256, 256>>>(n_nodes);
    hist_kernel<<<(n_edges + 255) / 256, 256>>>(dst, n_edges);
    scan1_kernel<<<nb, 1024>>>(n_nodes);
    gemm_kernel<<<(n_nodes + 127) / 128, 256,
                  GEMM_SMEM_FLOATS * (int)sizeof(float)>>>(feat, W, attn_l,
                                                           attn_r, n_nodes);
    scan23_kernel<<<nb, 1024>>>(n_nodes, nb);
    scatter_kernel<<<(n_edges + 255) / 256, 256>>>(src, dst, n_edges);
    node_kernel<<<(n_nodes * 32 + 255) / 256, 256>>>(bias, out, n_nodes);
}

// round 12
// speedup vs baseline: 1.1767x; 1.1767x over previous
#include <cuda_runtime.h>
#include <cstdint>
#include <cfloat>

#define N_NODES_MAX 100000
#define N_EDGES_MAX 1600000
#define FULL 0xFFFFFFFFu

typedef unsigned long long ull;

// ---------------- scratch (static device globals) ---------------------------
__device__ float4  g_h[N_NODES_MAX * 16];     // [N,64] projected features
__device__ float4  g_el[N_NODES_MAX];         // [N,4]
__device__ float4  g_er[N_NODES_MAX];         // [N,4]
__device__ int     g_cnt[N_NODES_MAX];        // in-degree
__device__ int     g_fill[N_NODES_MAX];       // scatter cursors
__device__ int     g_rowptr[N_NODES_MAX];     // exclusive prefix of cnt
__device__ int     g_blksum[128];
__device__ int     g_esrc[N_EDGES_MAX];       // CSR: src node per slot

__device__ __forceinline__ float leaky(float x) { return x > 0.f ? x : 0.2f * x; }

__device__ __forceinline__ ull pack2(float f) {
    ull r;
    asm("mov.b64 %0, {%1, %1};" : "=l"(r) : "f"(f));
    return r;
}
__device__ __forceinline__ void fma2(ull& acc, ull a, ull b) {
    asm("fma.rn.f32x2 %0, %1, %2, %0;" : "+l"(acc) : "l"(a), "l"(b));
}
__device__ __forceinline__ void unpack2(ull v, float& lo, float& hi) {
    asm("mov.b64 {%0, %1}, %2;" : "=f"(lo), "=f"(hi) : "l"(v));
}

// ---------------- kernel: zero counters -------------------------------------
__global__ void zero_kernel(int n_nodes) {
    int i = blockIdx.x * blockDim.x + threadIdx.x;
    if (i < n_nodes) { g_cnt[i] = 0; g_fill[i] = 0; }
}

// ---------------- kernel: in-degree histogram -------------------------------
__global__ void hist_kernel(const int* __restrict__ dst, int n_edges) {
    int e = blockIdx.x * blockDim.x + threadIdx.x;
    if (e < n_edges) atomicAdd(&g_cnt[dst[e]], 1);
}

// ---------------- scan: rowptr = exclusive_scan(cnt) ------------------------
__global__ __launch_bounds__(1024) void scan1_kernel(int n) {
    __shared__ int sh[1024];
    int i = blockIdx.x * 1024 + threadIdx.x;
    int v = (i < n) ? g_cnt[i] : 0;
    sh[threadIdx.x] = v;
    __syncthreads();
    for (int off = 1; off < 1024; off <<= 1) {
        int t = (threadIdx.x >= off) ? sh[threadIdx.x - off] : 0;
        __syncthreads();
        sh[threadIdx.x] += t;
        __syncthreads();
    }
    if (i < n) g_rowptr[i] = sh[threadIdx.x] - v;
    if (threadIdx.x == 1023) g_blksum[blockIdx.x] = sh[1023];
}
// merged scan2+scan3: each block computes prefix of blksum below it, adds.
__global__ __launch_bounds__(1024) void scan23_kernel(int n, int nb) {
    __shared__ int sh[128];
    const int t = threadIdx.x;
    if (t < 128) sh[t] = (t < nb && t < (int)blockIdx.x) ? g_blksum[t] : 0;
    __syncthreads();
    if (t < 64)  sh[t] += sh[t + 64];
    __syncthreads();
    if (t < 32) {
        int v = sh[t] + sh[t + 32];
#pragma unroll
        for (int o = 16; o; o >>= 1) v += __shfl_xor_sync(FULL, v, o);
        if (t == 0) sh[0] = v;
    }
    __syncthreads();
    const int off = sh[0];
    int i = blockIdx.x * 1024 + t;
    if (i < n) g_rowptr[i] += off;
}

// ---------------- kernel: CSR scatter ----------------------------------------
__global__ void scatter_kernel(const int* __restrict__ src,
                               const int* __restrict__ dst, int n_edges) {
    int e = blockIdx.x * blockDim.x + threadIdx.x;
    if (e >= n_edges) return;
    int d = dst[e];
    int r = atomicAdd(&g_fill[d], 1);
    g_esrc[g_rowptr[d] + r] = src[e];
}

// ---------------- kernel: h = feat @ W, el/er (double-buffered, f32x2) -------
#define FEATT_F   (32 * 128)
#define GEMM_SMEM_FLOATS (FEATT_F + 128 * 64 + 64 + 64 + 512 + 512)
__global__ __launch_bounds__(256, 3)
void gemm_kernel(const float* __restrict__ feat, const float* __restrict__ W,
                 const float* __restrict__ attn_l, const float* __restrict__ attn_r,
                 int n_nodes) {
    extern __shared__ float smem[];
    float* featT = smem;                       // [k%32][node] 32x128
    float* Wsh   = smem + FEATT_F;             // [k][col]  128x64
    float* alS   = Wsh + 8192;                 // 64
    float* arS   = alS + 64;                   // 64
    float* elS   = arS + 64;                   // [node][head] 128x4
    float* erS   = elS + 512;                  // 128x4

    const int tid  = threadIdx.x;
    const int tx   = tid & 31;
    const int ty   = tid >> 5;
    const int base = blockIdx.x * 128;

    for (int i = tid; i < 128 * 64; i += 256) Wsh[i] = W[i];
    if (tid < 64) { alS[tid] = attn_l[tid]; arS[tid] = attn_r[tid]; }
    if (tid < 128) {
        float4 z = make_float4(0.f, 0.f, 0.f, 0.f);
        ((float4*)elS)[tid] = z;
        ((float4*)erS)[tid] = z;
    }

    ull acc2[16];
#pragma unroll
    for (int j = 0; j < 16; j++) acc2[j] = 0ull;

    const float4* feat4 = (const float4*)feat;
    const int row  = tid & 127;
    const int c4b  = tid >> 7;
    const int node_s = base + row;
    const bool valid_s = (node_s < n_nodes);

    float4 pf[4];
#pragma unroll
    for (int j = 0; j < 4; j++) {
        int c4 = c4b + j * 2;
        pf[j] = valid_s ? feat4[node_s * 32 + 0 * 8 + c4]
                        : make_float4(0.f, 0.f, 0.f, 0.f);
    }

    for (int c = 0; c < 4; c++) {
        if (c) __syncthreads();
#pragma unroll
        for (int j = 0; j < 4; j++) {
            int c4 = c4b + j * 2;
            featT[(c4 * 4 + 0) * 128 + row] = pf[j].x;
            featT[(c4 * 4 + 1) * 128 + row] = pf[j].y;
            featT[(c4 * 4 + 2) * 128 + row] = pf[j].z;
            featT[(c4 * 4 + 3) * 128 + row] = pf[j].w;
        }
        __syncthreads();
        if (c < 3) {
#pragma unroll
            for (int j = 0; j < 4; j++) {
                int c4 = c4b + j * 2;
                pf[j] = valid_s ? feat4[node_s * 32 + (c + 1) * 8 + c4]
                                : make_float4(0.f, 0.f, 0.f, 0.f);
            }
        }

#pragma unroll 8
        for (int k = 0; k < 32; k++) {
            float4 f = *(const float4*)&featT[k * 128 + tx * 4];
            ull fd0 = pack2(f.x), fd1 = pack2(f.y);
            ull fd2 = pack2(f.z), fd3 = pack2(f.w);
            const ulonglong2* Wv =
                (const ulonglong2*)&Wsh[(c * 32 + k) * 64 + ty * 8];
            ulonglong2 wa = Wv[0];
            ulonglong2 wb = Wv[1];
            fma2(acc2[0],  fd0, wa.x); fma2(acc2[1],  fd0, wa.y);
            fma2(acc2[2],  fd0, wb.x); fma2(acc2[3],  fd0, wb.y);
            fma2(acc2[4],  fd1, wa.x); fma2(acc2[5],  fd1, wa.y);
            fma2(acc2[6],  fd1, wb.x); fma2(acc2[7],  fd1, wb.y);
            fma2(acc2[8],  fd2, wa.x); fma2(acc2[9],  fd2, wa.y);
            fma2(acc2[10], fd2, wb.x); fma2(acc2[11], fd2, wb.y);
            fma2(acc2[12], fd3, wa.x); fma2(acc2[13], fd3, wa.y);
            fma2(acc2[14], fd3, wb.x); fma2(acc2[15], fd3, wb.y);
        }
    }

    float o[4][8];
#pragma unroll
    for (int n = 0; n < 4; n++)
#pragma unroll
        for (int cp = 0; cp < 4; cp++)
            unpack2(acc2[n * 4 + cp], o[n][2 * cp], o[n][2 * cp + 1]);

    const int head = ty >> 1;
#pragma unroll
    for (int n = 0; n < 4; n++) {
        float sl = 0.f, sr = 0.f;
#pragma unroll
        for (int cc = 0; cc < 8; cc++) {
            int col = ty * 8 + cc;
            sl += o[n][cc] * alS[col];
            sr += o[n][cc] * arS[col];
        }
        int node_l = tx * 4 + n;
        atomicAdd(&elS[node_l * 4 + head], sl);
        atomicAdd(&erS[node_l * 4 + head], sr);
    }

    float* g_h_f = (float*)g_h;
#pragma unroll
    for (int n = 0; n < 4; n++) {
        int node = base + tx * 4 + n;
        if (node < n_nodes) {
            float* p = g_h_f + node * 64 + ty * 8;
            *(float4*)p       = make_float4(o[n][0], o[n][1], o[n][2], o[n][3]);
            *(float4*)(p + 4) = make_float4(o[n][4], o[n][5], o[n][6], o[n][7]);
        }
    }

    __syncthreads();
    if (tid < 128) {
        int node = base + tid;
        if (node < n_nodes) {
            g_el[node] = ((const float4*)elS)[tid];
            g_er[node] = ((const float4*)erS)[tid];
        }
    }
}

// ---------------- kernel: fused softmax + aggregation (2 nodes per warp) -----
// half-warp per node; lane owns 4 output cols (float4). One LDG.128 serves two
// edges (one per half). Lane-parallel exp (16 edges per half per batch) staged
// in smem; den via 4-step half-warp reduce.
__global__ __launch_bounds__(256)
void node_kernel(const float* __restrict__ bias, float* __restrict__ out,
                 int n_nodes) {
    __shared__ float4 sm_ex[8][32];    // [warp][edge slot]
    const int warp_g = (blockIdx.x * blockDim.x + threadIdx.x) >> 5;
    const int w      = threadIdx.x >> 5;
    const int lane   = threadIdx.x & 31;
    const int half   = lane >> 4;      // 0: node A, 1: node B
    const int hl     = lane & 15;      // lane within half = col group
    const int n_pairs = (n_nodes + 1) >> 1;
    if (warp_g >= n_pairs) return;

    const int node   = warp_g * 2 + half;
    const bool nvalid = (node < n_nodes);
    const int base = nvalid ? g_rowptr[node] : 0;
    const int deg  = nvalid ? g_cnt[node]   : 0;
    const int hd   = hl >> 2;          // head of this lane's 4 cols

    const float4 b4 = ((const float4*)bias)[hl];
    float4 er4 = nvalid ? g_er[node] : make_float4(0.f, 0.f, 0.f, 0.f);

    const float4* h4 = (const float4*)g_h;
    float* smf = (float*)sm_ex[w];

    float4 acc  = make_float4(0.f, 0.f, 0.f, 0.f);
    float4 den4 = make_float4(0.f, 0.f, 0.f, 0.f);

    int nb = (deg + 15) >> 4;
    int mb = max(nb, __shfl_xor_sync(FULL, nb, 16));

    for (int b = 0; b < mb; b++) {
        const int idx = b * 16 + hl;
        const int s_own = (idx < deg) ? g_esrc[base + idx] : 0;

        // lane-parallel exp: one edge per lane (16 per half)
        float4 ex = make_float4(0.f, 0.f, 0.f, 0.f);
        if (idx < deg) {
            float4 a = g_el[s_own];
            ex.x = __expf(leaky(a.x + er4.x));
            ex.y = __expf(leaky(a.y + er4.y));
            ex.z = __expf(leaky(a.z + er4.z));
            ex.w = __expf(leaky(a.w + er4.w));
        }
        den4.x += ex.x; den4.y += ex.y; den4.z += ex.z; den4.w += ex.w;
        __syncwarp();
        sm_ex[w][lane] = ex;
        __syncwarp();

        int cnt = min(16, deg - b * 16);               // may be <= 0
        int cmax = max(cnt, __shfl_xor_sync(FULL, cnt, 16));
#pragma unroll 8
        for (int i = 0; i < cmax; i++) {
            int s   = __shfl_sync(FULL, s_own, (half << 4) + i);
            float a = smf[((half << 4) + i) * 4 + hd]; // 0 when half exhausted
            float4 v = h4[s * 16 + hl];
            acc.x += a * v.x; acc.y += a * v.y;
            acc.z += a * v.z; acc.w += a * v.w;
        }
    }

    // half-warp denominator reduce (offsets < 16 stay within half)
#pragma unroll
    for (int o = 8; o; o >>= 1) {
        den4.x += __shfl_xor_sync(FULL, den4.x, o);
        den4.y += __shfl_xor_sync(FULL, den4.y, o);
        den4.z += __shfl_xor_sync(FULL, den4.z, o);
        den4.w += __shfl_xor_sync(FULL, den4.w, o);
    }
    const float den = hd == 0 ? den4.x : hd == 1 ? den4.y : hd == 2 ? den4.z : den4.w;
    const float rd  = den > 0.f ? 1.f / den : 0.f;

    if (nvalid)
        ((float4*)out)[node * 16 + hl] =
            make_float4(acc.x * rd + b4.x, acc.y * rd + b4.y,
                        acc.z * rd + b4.z, acc.w * rd + b4.w);
}

// ---------------- launcher --------------------------------------------------
extern "C" void kernel_launch(void* const* d_in, const int* in_sizes, int n_in,
                              void* d_out, int out_size) {
    const float* feat   = (const float*)d_in[0];
    const float* W      = (const float*)d_in[1];
    const float* attn_l = (const float*)d_in[2];
    const float* attn_r = (const float*)d_in[3];
    const float* bias   = (const float*)d_in[4];
    const int*   src    = (const int*)d_in[5];
    const int*   dst    = (const int*)d_in[6];
    float*       out    = (float*)d_out;

    const int n_nodes = in_sizes[0] / 128;
    const int n_edges = in_sizes[5];
    const int nb      = (n_nodes + 1023) / 1024;
    const int n_pairs = (n_nodes + 1) / 2;

    cudaFuncSetAttribute(gemm_kernel, cudaFuncAttributeMaxDynamicSharedMemorySize,
                         GEMM_SMEM_FLOATS * (int)sizeof(float));

    // gemm placed 4th: ncu captures launch #4
    zero_kernel<<<(n_nodes + 255) / 256, 256>>>(n_nodes);
    hist_kernel<<<(n_edges + 255) / 256, 256>>>(dst, n_edges);
    scan1_kernel<<<nb, 1024>>>(n_nodes);
    gemm_kernel<<<(n_nodes + 127) / 128, 256,
                  GEMM_SMEM_FLOATS * (int)sizeof(float)>>>(feat, W, attn_l,
                                                           attn_r, n_nodes);
    scan23_kernel<<<nb, 1024>>>(n_nodes, nb);
    scatter_kernel<<<(n_edges + 255) / 256, 256>>>(src, dst, n_edges);
    node_kernel<<<(n_pairs * 32 + 255) / 256, 256>>>(bias, out, n_nodes);
}